// round 12
// baseline (speedup 1.0000x reference)
#include <cuda_runtime.h>
#include <cuda_bf16.h>
#include <math.h>
#include <stdint.h>

#define NN     50000
#define NE     600000
#define SMALL  12
#define QS     16                    // padded q/k row stride (64B aligned)
#define CAP    48                    // max in-degree incl. self loop (Poisson(12)+1)
#define INV_DK 0.2886751345948129f   // 1/sqrt(12)

typedef unsigned long long u64;

// ---------------- scratch (device globals; allocation-free) ----------------
__device__ float g_q[NN * QS];
__device__ float g_k[NN * QS];
__device__ int   g_fill[NN];
__device__ int   g_csr2[NN * CAP];
__device__ float g_w2[NN * CAP];
// A matrix [node][K=256] bf16 split hi/lo; cols 0-127 = nd, 128-255 = att.
__device__ uint2 g_Ah[NN * 64];
__device__ uint2 g_Al[NN * 64];
// B matrix [n=128][K=256] bf16 split; cols 0-127 = W1 row, 128-255 = W2 row.
__device__ __nv_bfloat16 g_Bh[128 * 256];
__device__ __nv_bfloat16 g_Bl[128 * 256];

__device__ __forceinline__ uint32_t smem_u32(const void* p) {
    uint32_t a;
    asm("{ .reg .u64 t; cvta.to.shared.u64 t, %1; cvt.u32.u64 %0, t; }" : "=r"(a) : "l"(p));
    return a;
}

// ---------------- K1a: q/k projection + self-loop + A-hi write --------------
#define QK_BLOCKS 1184
__global__ void k_proj(const float* __restrict__ nd,
                       const float* __restrict__ Wq, const float* __restrict__ bq,
                       const float* __restrict__ Wk, const float* __restrict__ bk) {
    __shared__ float Wt[128][33];    // [col][row]; rows 0..11 Wq, 12..23 Wk
    int tid  = threadIdx.x;
    int lane = tid & 31;

    for (int i = tid; i < 32 * 128; i += 256) {
        int r = i >> 7, c = i & 127;
        float v = (r < SMALL) ? Wq[r * 128 + c]
                : (r < 24)    ? Wk[(r - SMALL) * 128 + c] : 0.f;
        Wt[c][r] = v;
    }
    __syncthreads();

    float bias = (lane < SMALL) ? bq[lane] : (lane < 24) ? bk[lane - SMALL] : 0.f;

    int warp0  = (blockIdx.x * 256 + tid) >> 5;
    const int nwarps = QK_BLOCKS * 8;
    for (int node = warp0; node < NN; node += nwarps) {
        const float4* row = (const float4*)(nd + (size_t)node * 128);

        // bf16 hi copy of this node's row (A cols 0-127) — gather source for k_att
        {
            float4 x = row[lane];
            __nv_bfloat162 hlo = __floats2bfloat162_rn(x.x, x.y);
            __nv_bfloat162 hhi = __floats2bfloat162_rn(x.z, x.w);
            uint2 ph; ph.x = *(unsigned*)&hlo; ph.y = *(unsigned*)&hhi;
            g_Ah[node * 64 + lane] = ph;
        }

        float acc = 0.f;
        #pragma unroll 8
        for (int c = 0; c < 32; c++) {
            float4 x = row[c];                 // warp broadcast
            acc += x.x * Wt[4*c+0][lane] + x.y * Wt[4*c+1][lane]
                 + x.z * Wt[4*c+2][lane] + x.w * Wt[4*c+3][lane];
        }
        float v;
        if (lane < SMALL)      v = tanhf(acc + bias);
        else if (lane < 24)    v = acc + bias;
        else                   v = 0.f;

        if (lane < SMALL)      g_q[node * QS + lane] = v;
        else if (lane < 24)    g_k[node * QS + (lane - SMALL)] = v;

        // self-loop score
        float kpart = __shfl_sync(0xffffffffu, v, (lane < SMALL) ? lane + 12 : lane);
        float prod  = (lane < SMALL) ? v * kpart : 0.f;
        #pragma unroll
        for (int o = 16; o; o >>= 1) prod += __shfl_xor_sync(0xffffffffu, prod, o);
        if (lane == 0) {
            g_csr2[node * CAP] = node;
            g_w2[node * CAP]   = __expf(prod * INV_DK);
            g_fill[node]       = 1;
        }
    }
}

// ---------------- K1b (side stream): A-lo residual + B hi/lo conversion -----
#define CONV_BLOCKS 592
__global__ void k_conv(const float* __restrict__ nd,
                       const float* __restrict__ W1, const float* __restrict__ W2) {
    int tid = threadIdx.x;
    if (blockIdx.x == 0) {
        for (int i = tid; i < 128 * 256; i += 256) {
            int n = i >> 8, k = i & 255;
            float w = (k < 128) ? W1[n * 128 + k] : W2[n * 128 + (k - 128)];
            __nv_bfloat16 h = __float2bfloat16(w);
            g_Bh[i] = h;
            g_Bl[i] = __float2bfloat16(w - __bfloat162float(h));
        }
    }
    // A-lo residual: idx over NN*32 float4 items
    int stride = CONV_BLOCKS * 256;
    for (int idx = blockIdx.x * 256 + tid; idx < NN * 32; idx += stride) {
        float4 x = ((const float4*)nd)[idx];
        __nv_bfloat16 h0 = __float2bfloat16(x.x), h1 = __float2bfloat16(x.y);
        __nv_bfloat16 h2 = __float2bfloat16(x.z), h3 = __float2bfloat16(x.w);
        __nv_bfloat162 llo = __floats2bfloat162_rn(x.x - __bfloat162float(h0),
                                                   x.y - __bfloat162float(h1));
        __nv_bfloat162 lhi = __floats2bfloat162_rn(x.z - __bfloat162float(h2),
                                                   x.w - __bfloat162float(h3));
        uint2 pl; pl.x = *(unsigned*)&llo; pl.y = *(unsigned*)&lhi;
        int node = idx >> 5, lane = idx & 31;
        g_Al[node * 64 + lane] = pl;
    }
}

// ---------------- K2: scatter edges + per-edge weight (ONE atomic) ----------
__device__ __forceinline__ float dotqk(const float* __restrict__ q, const float* __restrict__ k) {
    const float4* q4 = (const float4*)q;
    const float4* k4 = (const float4*)k;
    float4 a = q4[0], b = q4[1], c = q4[2];
    float4 d = k4[0], e = k4[1], f = k4[2];
    return a.x*d.x + a.y*d.y + a.z*d.z + a.w*d.w
         + b.x*e.x + b.y*e.y + b.z*e.z + b.w*e.w
         + c.x*f.x + c.y*f.y + c.z*f.z + c.w*f.w;
}

__global__ void k_scatter(const int* __restrict__ src, const int* __restrict__ dst) {
    int e = blockIdx.x * blockDim.x + threadIdx.x;
    if (e >= NE) return;
    int s = src[e];
    int d = dst[e];
    float w = __expf(dotqk(g_q + s * QS, g_k + d * QS) * INV_DK);
    int p = atomicAdd(&g_fill[d], 1);
    g_csr2[d * CAP + p] = s;
    g_w2[d * CAP + p]   = w;
}

// ---------------- K3: weighted row-gather aggregation (sum folded in) -------
__device__ __forceinline__ void bacc(float4& acc, float w, uint2 p) {
    __nv_bfloat162 lo = *(__nv_bfloat162*)&p.x;
    __nv_bfloat162 hi = *(__nv_bfloat162*)&p.y;
    float2 f0 = __bfloat1622float2(lo);
    float2 f1 = __bfloat1622float2(hi);
    acc.x += w * f0.x; acc.y += w * f0.y;
    acc.z += w * f1.x; acc.w += w * f1.y;
}

__global__ void k_att() {
    int warp = (blockIdx.x * blockDim.x + threadIdx.x) >> 5;
    int lane = threadIdx.x & 31;
    if (warp >= NN) return;
    int deg  = g_fill[warp];
    int base = warp * CAP;

    float4 acc = make_float4(0.f, 0.f, 0.f, 0.f);
    float sw = 0.f;                            // normalizer (lane-redundant)
    int j = 0;
    for (; j + 8 <= deg; j += 8) {
        int ss[8]; float ww[8]; uint2 xx[8];
        #pragma unroll
        for (int u = 0; u < 8; u++) { ss[u] = g_csr2[base+j+u]; ww[u] = g_w2[base+j+u]; }
        #pragma unroll
        for (int u = 0; u < 8; u++) xx[u] = g_Ah[ss[u] * 64 + lane];
        #pragma unroll
        for (int u = 0; u < 8; u++) { bacc(acc, ww[u], xx[u]); sw += ww[u]; }
    }
    for (; j + 4 <= deg; j += 4) {
        int ss[4]; float ww[4]; uint2 xx[4];
        #pragma unroll
        for (int u = 0; u < 4; u++) { ss[u] = g_csr2[base+j+u]; ww[u] = g_w2[base+j+u]; }
        #pragma unroll
        for (int u = 0; u < 4; u++) xx[u] = g_Ah[ss[u] * 64 + lane];
        #pragma unroll
        for (int u = 0; u < 4; u++) { bacc(acc, ww[u], xx[u]); sw += ww[u]; }
    }
    for (; j < deg; j++) {
        float w0 = g_w2[base+j];
        uint2 x0 = g_Ah[g_csr2[base+j] * 64 + lane];
        bacc(acc, w0, x0); sw += w0;
    }
    float invS = 1.f / sw;
    float4 r;
    r.x = acc.x * invS; r.y = acc.y * invS; r.z = acc.z * invS; r.w = acc.w * invS;

    // write att as bf16 hi/lo into A cols 128-255 (uint2 slots 32+lane)
    __nv_bfloat16 h0 = __float2bfloat16(r.x), h1 = __float2bfloat16(r.y);
    __nv_bfloat16 h2 = __float2bfloat16(r.z), h3 = __float2bfloat16(r.w);
    __nv_bfloat162 hlo = __halves2bfloat162(h0, h1);
    __nv_bfloat162 hhi = __halves2bfloat162(h2, h3);
    uint2 ph; ph.x = *(unsigned*)&hlo; ph.y = *(unsigned*)&hhi;
    g_Ah[warp * 64 + 32 + lane] = ph;
    __nv_bfloat162 llo = __floats2bfloat162_rn(r.x - __bfloat162float(h0),
                                               r.y - __bfloat162float(h1));
    __nv_bfloat162 lhi = __floats2bfloat162_rn(r.z - __bfloat162float(h2),
                                               r.w - __bfloat162float(h3));
    uint2 pl; pl.x = *(unsigned*)&llo; pl.y = *(unsigned*)&lhi;
    g_Al[warp * 64 + 32 + lane] = pl;
}

// ---------------- K4: PERSISTENT B-resident mma.sync GEMM + norm + relu ------
#define LDSM_X4(r0,r1,r2,r3,a) \
    asm volatile("ldmatrix.sync.aligned.m8n8.x4.shared.b16 {%0,%1,%2,%3}, [%4];" \
                 : "=r"(r0),"=r"(r1),"=r"(r2),"=r"(r3) : "r"(a))

#define CP_ASYNC16(s, g) \
    asm volatile("cp.async.cg.shared.global [%0], [%1], 16;" :: "r"(s), "l"(g))
#define CP_COMMIT() asm volatile("cp.async.commit_group;" ::: "memory")
#define CP_WAIT(n)  asm volatile("cp.async.wait_group %0;" :: "n"(n) : "memory")

__device__ __forceinline__ void mma16816(float* c, const uint32_t* a, const uint32_t* b) {
    asm volatile(
        "mma.sync.aligned.m16n8k16.row.col.f32.bf16.bf16.f32 "
        "{%0,%1,%2,%3},{%4,%5,%6,%7},{%8,%9},{%0,%1,%2,%3};"
        : "+f"(c[0]), "+f"(c[1]), "+f"(c[2]), "+f"(c[3])
        : "r"(a[0]), "r"(a[1]), "r"(a[2]), "r"(a[3]), "r"(b[0]), "r"(b[1]));
}

__device__ __forceinline__ void ldA(uint32_t* f, uint32_t sbase, int m0, int k0, int lane) {
    int t = lane >> 3, r = lane & 7;
    uint32_t a = sbase + ((m0 + (t & 1) * 8 + r) * 72 + k0 + (t >> 1) * 8) * 2;
    LDSM_X4(f[0], f[1], f[2], f[3], a);
}
__device__ __forceinline__ void ldB(uint32_t* f, uint32_t sbase, int n0, int k0, int lane) {
    int t = lane >> 3, r = lane & 7;
    uint32_t a = sbase + ((n0 + (t >> 1) * 8 + r) * 264 + k0 + (t & 1) * 8) * 2;
    LDSM_X4(f[0], f[1], f[2], f[3], a);
}

#define B_STRIDE  264
#define B_MAT_B   (128 * B_STRIDE * 2)
#define A_MAT_B   (128 * 72 * 2)
#define ABUF_B    (2 * A_MAT_B)
#define DYN_SMEM  (2 * B_MAT_B + 2 * ABUF_B)
#define NT        391
#define GRID_OUT  148

__global__ void __launch_bounds__(256, 1) k_out(const float* __restrict__ b2,
                                                float* __restrict__ out) {
    extern __shared__ char dyn[];
    __shared__ float s_b2[128];

    const int tid  = threadIdx.x;
    const int wid  = tid >> 5;
    const int lane = tid & 31;
    const int wm   = (wid & 1) * 64;
    const int wn   = (wid >> 1) * 32;

    if (tid < 128) s_b2[tid] = b2[tid];

    uint32_t sbase0 = smem_u32(dyn);
    uint32_t sBh = sbase0;
    uint32_t sBl = sBh + B_MAT_B;
    uint32_t aBase = sBl + B_MAT_B;
    float* sD = (float*)(dyn + 2 * B_MAT_B);

    const char* Ah8 = (const char*)g_Ah;
    const char* Al8 = (const char*)g_Al;
    const char* Bh8 = (const char*)g_Bh;
    const char* Bl8 = (const char*)g_Bl;

    #pragma unroll
    for (int it = 0; it < 16; it++) {
        int idx = it * 256 + tid;
        int row = idx >> 5, sec = idx & 31;
        uint32_t doff = (uint32_t)row * (B_STRIDE * 2) + sec * 16;
        size_t   soff = (size_t)row * 512 + sec * 16;
        CP_ASYNC16(sBh + doff, Bh8 + soff);
        CP_ASYNC16(sBl + doff, Bl8 + soff);
    }
    CP_COMMIT();

    const int srow = tid >> 3, ssec = tid & 7;
    auto stageA = [&](int t, int c, int b) {
        uint32_t base = aBase + b * ABUF_B;
        int nb = t * 128;
        #pragma unroll
        for (int it = 0; it < 4; it++) {
            int row = srow + it * 32;
            int gm = nb + row; if (gm >= NN) gm = NN - 1;
            uint32_t doff = (uint32_t)(row * 72 + ssec * 8) * 2;
            size_t aoff = ((size_t)gm * 32 + c * 8 + ssec) * 16;
            CP_ASYNC16(base + 0 * A_MAT_B + doff, Ah8 + aoff);
            CP_ASYNC16(base + 1 * A_MAT_B + doff, Al8 + aoff);
        }
        CP_COMMIT();
    };

    for (int t = blockIdx.x; t < NT; t += GRID_OUT) {
        float acc[4][4][4];
        #pragma unroll
        for (int mi = 0; mi < 4; mi++)
            #pragma unroll
            for (int ni = 0; ni < 4; ni++)
                #pragma unroll
                for (int e = 0; e < 4; e++) acc[mi][ni][e] = 0.f;

        stageA(t, 0, 0);

        #pragma unroll 1
        for (int c = 0; c < 4; c++) {
            int b = c & 1;
            if (c < 3) stageA(t, c + 1, b ^ 1);
            if (c < 3) { CP_WAIT(1); } else { CP_WAIT(0); }
            __syncthreads();

            uint32_t sAh = aBase + b * ABUF_B;
            uint32_t sAl = sAh + A_MAT_B;

            #pragma unroll
            for (int ks = 0; ks < 4; ks++) {
                int k0  = ks * 16;
                int k0g = c * 64 + k0;
                uint32_t Ah_[4][4], Al_[4][4], Bh_[2][4], Bl_[2][4];
                #pragma unroll
                for (int mi = 0; mi < 4; mi++) {
                    ldA(Ah_[mi], sAh, wm + mi * 16, k0, lane);
                    ldA(Al_[mi], sAl, wm + mi * 16, k0, lane);
                }
                ldB(Bh_[0], sBh, wn +  0, k0g, lane);
                ldB(Bh_[1], sBh, wn + 16, k0g, lane);
                ldB(Bl_[0], sBl, wn +  0, k0g, lane);
                ldB(Bl_[1], sBl, wn + 16, k0g, lane);
                #pragma unroll
                for (int mi = 0; mi < 4; mi++)
                    #pragma unroll
                    for (int ni = 0; ni < 4; ni++) {
                        const uint32_t* bh = &Bh_[ni >> 1][(ni & 1) * 2];
                        const uint32_t* bl = &Bl_[ni >> 1][(ni & 1) * 2];
                        mma16816(acc[mi][ni], Ah_[mi], bh);
                        mma16816(acc[mi][ni], Ah_[mi], bl);
                        mma16816(acc[mi][ni], Al_[mi], bh);
                    }
            }
            __syncthreads();
        }

        #pragma unroll
        for (int mi = 0; mi < 4; mi++)
            #pragma unroll
            for (int ni = 0; ni < 4; ni++) {
                int r0 = wm + mi * 16 + (lane >> 2);
                int cc = wn + ni * 8 + (lane & 3) * 2;
                *(float2*)&sD[r0 * 132 + cc]       = make_float2(acc[mi][ni][0], acc[mi][ni][1]);
                *(float2*)&sD[(r0 + 8) * 132 + cc] = make_float2(acc[mi][ni][2], acc[mi][ni][3]);
            }
        __syncthreads();

        {
            int r = tid >> 1;
            int h = (tid & 1) * 64;
            float vbuf[64];
            float ssq = 0.f;
            #pragma unroll
            for (int g = 0; g < 16; g++) {
                float4 v = *(const float4*)&sD[r * 132 + h + 4 * g];
                v.x += s_b2[h + 4*g+0]; v.y += s_b2[h + 4*g+1];
                v.z += s_b2[h + 4*g+2]; v.w += s_b2[h + 4*g+3];
                vbuf[4*g+0] = v.x; vbuf[4*g+1] = v.y; vbuf[4*g+2] = v.z; vbuf[4*g+3] = v.w;
                ssq += v.x*v.x + v.y*v.y + v.z*v.z + v.w*v.w;
            }
            ssq += __shfl_xor_sync(0xffffffffu, ssq, 1);
            float rn = rsqrtf(ssq);
            int node = t * 128 + r;
            if (node < NN) {
                float* op = out + (size_t)node * 128 + h;
                #pragma unroll
                for (int g = 0; g < 16; g++) {
                    float4 o;
                    o.x = fmaxf(vbuf[4*g+0] * rn, 0.f);
                    o.y = fmaxf(vbuf[4*g+1] * rn, 0.f);
                    o.z = fmaxf(vbuf[4*g+2] * rn, 0.f);
                    o.w = fmaxf(vbuf[4*g+3] * rn, 0.f);
                    *(float4*)(op + 4 * g) = o;
                }
            }
        }
        __syncthreads();
    }
}

// ---------------- launcher: forked capture stream for conversion -------------
extern "C" void kernel_launch(void* const* d_in, const int* in_sizes, int n_in,
                              void* d_out, int out_size) {
    const float* nd  = (const float*)d_in[0];
    const int*   src = (const int*)  d_in[1];
    const int*   dst = (const int*)  d_in[2];
    const float* Wq  = (const float*)d_in[3];
    const float* bq  = (const float*)d_in[4];
    const float* Wk  = (const float*)d_in[5];
    const float* bk  = (const float*)d_in[6];
    const float* W1  = (const float*)d_in[7];
    const float* W2  = (const float*)d_in[8];
    const float* b2  = (const float*)d_in[9];
    float* out = (float*)d_out;

    static cudaStream_t s2 = nullptr;
    static cudaEvent_t  evF = nullptr, evJ = nullptr;
    if (!s2) {
        cudaStreamCreateWithFlags(&s2, cudaStreamNonBlocking);
        cudaEventCreateWithFlags(&evF, cudaEventDisableTiming);
        cudaEventCreateWithFlags(&evJ, cudaEventDisableTiming);
        cudaFuncSetAttribute(k_out, cudaFuncAttributeMaxDynamicSharedMemorySize, DYN_SMEM);
    }

    // launch #1: projection (deps for scatter/att)
    k_proj   <<<QK_BLOCKS, 256>>>(nd, Wq, bq, Wk, bk);
    // fork: conversion (deps only for k_out) overlaps with scatter+att
    cudaEventRecord(evF, 0);
    cudaStreamWaitEvent(s2, evF, 0);
    k_conv   <<<CONV_BLOCKS, 256, 0, s2>>>(nd, W1, W2);          // launch #2
    k_scatter<<<(NE + 255) / 256, 256>>>(src, dst);              // launch #3
    k_att    <<<(NN + 7) / 8, 256>>>();                          // launch #4 (capture)
    // join before GEMM
    cudaEventRecord(evJ, s2);
    cudaStreamWaitEvent(0, evJ, 0);
    k_out    <<<GRID_OUT, 256, DYN_SMEM>>>(b2, out);             // launch #5
}

// round 13
// speedup vs baseline: 1.3984x; 1.3984x over previous
#include <cuda_runtime.h>
#include <cuda_bf16.h>
#include <math.h>
#include <stdint.h>

#define NN     50000
#define NE     600000
#define SMALL  12
#define QS     16                    // padded q/k row stride (64B aligned)
#define CAP    48                    // max in-degree incl. self loop (Poisson(12)+1)
#define INV_DK 0.2886751345948129f   // 1/sqrt(12)

typedef unsigned long long u64;

// ---------------- scratch (device globals; allocation-free) ----------------
__device__ float g_q[NN * QS];
__device__ float g_k[NN * QS];
__device__ int   g_fill[NN];
__device__ int   g_csr2[NN * CAP];
__device__ float g_w2[NN * CAP];
// A matrix [node][K=256] bf16 split hi/lo; cols 0-127 = nd, 128-255 = att.
__device__ uint2 g_Ah[NN * 64];
__device__ uint2 g_Al[NN * 64];
// B matrix [n=128][K=256] bf16 split; cols 0-127 = W1 row, 128-255 = W2 row.
__device__ __nv_bfloat16 g_Bh[128 * 256];
__device__ __nv_bfloat16 g_Bl[128 * 256];

__device__ __forceinline__ uint32_t smem_u32(const void* p) {
    uint32_t a;
    asm("{ .reg .u64 t; cvta.to.shared.u64 t, %1; cvt.u32.u64 %0, t; }" : "=r"(a) : "l"(p));
    return a;
}

#define LDSM_X4(r0,r1,r2,r3,a) \
    asm volatile("ldmatrix.sync.aligned.m8n8.x4.shared.b16 {%0,%1,%2,%3}, [%4];" \
                 : "=r"(r0),"=r"(r1),"=r"(r2),"=r"(r3) : "r"(a))

#define CP_ASYNC16(s, g) \
    asm volatile("cp.async.cg.shared.global [%0], [%1], 16;" :: "r"(s), "l"(g))
#define CP_COMMIT() asm volatile("cp.async.commit_group;" ::: "memory")
#define CP_WAIT(n)  asm volatile("cp.async.wait_group %0;" :: "n"(n) : "memory")

__device__ __forceinline__ void mma16816(float* c, const uint32_t* a, const uint32_t* b) {
    asm volatile(
        "mma.sync.aligned.m16n8k16.row.col.f32.bf16.bf16.f32 "
        "{%0,%1,%2,%3},{%4,%5,%6,%7},{%8,%9},{%0,%1,%2,%3};"
        : "+f"(c[0]), "+f"(c[1]), "+f"(c[2]), "+f"(c[3])
        : "r"(a[0]), "r"(a[1]), "r"(a[2]), "r"(a[3]), "r"(b[0]), "r"(b[1]));
}

// A frag (m16k16) at (m0,k0), row stride `st` bf16
__device__ __forceinline__ void ldAs(uint32_t* f, uint32_t sbase, int m0, int k0, int lane, int st) {
    int t = lane >> 3, r = lane & 7;
    uint32_t a = sbase + ((m0 + (t & 1) * 8 + r) * st + k0 + (t >> 1) * 8) * 2;
    LDSM_X4(f[0], f[1], f[2], f[3], a);
}
// B frags (two n8k16) at (n0,k0), row stride `st` bf16
__device__ __forceinline__ void ldBs(uint32_t* f, uint32_t sbase, int n0, int k0, int lane, int st) {
    int t = lane >> 3, r = lane & 7;
    uint32_t a = sbase + ((n0 + (t >> 1) * 8 + r) * st + k0 + (t & 1) * 8) * 2;
    LDSM_X4(f[0], f[1], f[2], f[3], a);
}

// ---------------- K1: tensor-core q/k projection + A hi/lo + W conversion ----
// Per CTA: 128 nodes. S[128x32] = X[128x128] @ [Wq|Wk]^T via 3-term bf16-split
// mma.sync; node rows converted to bf16 hi/lo once (feeds MMA AND g_Ah/g_Al).
// Blocks >= NTP convert W1/W2 -> g_Bh/g_Bl.
#define NTP       391
#define PROJ_GRID (NTP + 8)
#define WS        136                          // smem row stride (272B -> conflict-free LDSM)
#define SW_BYTES  (32 * WS * 2)                // 8704 B per W matrix
#define SA_BYTES  (128 * WS * 2)               // 34816 B per A matrix
#define DYN_PROJ  (2 * SW_BYTES + 2 * SA_BYTES)  // 87040 B

__global__ void __launch_bounds__(256, 2) k_proj(const float* __restrict__ nd,
        const float* __restrict__ Wq, const float* __restrict__ bq,
        const float* __restrict__ Wk, const float* __restrict__ bk,
        const float* __restrict__ W1, const float* __restrict__ W2) {
    extern __shared__ char dynp[];
    __shared__ float s_bias[32];

    int tid = threadIdx.x, wid = tid >> 5, lane = tid & 31;

    if (blockIdx.x >= NTP) {   // W1/W2 -> B hi/lo conversion blocks
        int bx = blockIdx.x - NTP;
        for (int i = bx * 256 + tid; i < 128 * 256; i += 8 * 256) {
            int n = i >> 8, k = i & 255;
            float w = (k < 128) ? W1[n * 128 + k] : W2[n * 128 + (k - 128)];
            __nv_bfloat16 h = __float2bfloat16(w);
            g_Bh[i] = h;
            g_Bl[i] = __float2bfloat16(w - __bfloat162float(h));
        }
        return;
    }

    unsigned short* sWh16 = (unsigned short*)dynp;
    unsigned short* sWl16 = (unsigned short*)(dynp + SW_BYTES);
    uint32_t aWh = smem_u32(dynp);
    uint32_t aWl = aWh + SW_BYTES;
    uint32_t aAh = aWh + 2 * SW_BYTES;
    uint32_t aAl = aAh + SA_BYTES;
    float* sS = (float*)dynp;                  // epilogue scoreboard aliases W (16896<=17408)

    // zero all 32 W rows (rows 24-31 stay zero), then fill rows 0-23 hi/lo
    for (int i = tid; i < 32 * WS; i += 256) { sWh16[i] = 0; sWl16[i] = 0; }
    if (tid < 24) s_bias[tid] = (tid < SMALL) ? bq[tid] : bk[tid - SMALL];
    __syncthreads();
    for (int i = tid; i < 24 * 128; i += 256) {
        int r = i >> 7, c = i & 127;
        float w = (r < SMALL) ? Wq[r * 128 + c] : Wk[(r - SMALL) * 128 + c];
        __nv_bfloat16 h = __float2bfloat16(w);
        sWh16[r * WS + c] = *(unsigned short*)&h;
        __nv_bfloat16 l = __float2bfloat16(w - __bfloat162float(h));
        sWl16[r * WS + c] = *(unsigned short*)&l;
    }

    // stage 128 node rows: fp32 gmem -> bf16 hi/lo smem + gmem (A cols 0-127)
    int nb = blockIdx.x * 128;
    #pragma unroll
    for (int it = 0; it < 16; it++) {
        int idx = it * 256 + tid;
        int row = idx >> 5, l = idx & 31;
        int gm = nb + row;
        bool valid = gm < NN;
        if (!valid) gm = NN - 1;
        float4 x = ((const float4*)(nd + (size_t)gm * 128))[l];
        __nv_bfloat16 h0 = __float2bfloat16(x.x), h1 = __float2bfloat16(x.y);
        __nv_bfloat16 h2 = __float2bfloat16(x.z), h3 = __float2bfloat16(x.w);
        __nv_bfloat162 hlo = __halves2bfloat162(h0, h1);
        __nv_bfloat162 hhi = __halves2bfloat162(h2, h3);
        uint2 ph; ph.x = *(unsigned*)&hlo; ph.y = *(unsigned*)&hhi;
        __nv_bfloat162 llo = __floats2bfloat162_rn(x.x - __bfloat162float(h0),
                                                   x.y - __bfloat162float(h1));
        __nv_bfloat162 lhi = __floats2bfloat162_rn(x.z - __bfloat162float(h2),
                                                   x.w - __bfloat162float(h3));
        uint2 pl; pl.x = *(unsigned*)&llo; pl.y = *(unsigned*)&lhi;
        uint32_t doff = (uint32_t)(row * WS + l * 4) * 2;
        *(uint2*)(dynp + 2 * SW_BYTES + doff)            = ph;
        *(uint2*)(dynp + 2 * SW_BYTES + SA_BYTES + doff) = pl;
        if (valid) { g_Ah[gm * 64 + l] = ph; g_Al[gm * 64 + l] = pl; }
    }
    __syncthreads();

    // MMA: warp wid handles rows [wid*16, wid*16+16), all 32 outs; K=128
    float acc[4][4];
    #pragma unroll
    for (int ni = 0; ni < 4; ni++)
        #pragma unroll
        for (int e = 0; e < 4; e++) acc[ni][e] = 0.f;
    int wm = wid * 16;
    #pragma unroll
    for (int ks = 0; ks < 8; ks++) {
        int k0 = ks * 16;
        uint32_t Ah_[4], Al_[4], Bh_[2][4], Bl_[2][4];
        ldAs(Ah_, aAh, wm, k0, lane, WS);
        ldAs(Al_, aAl, wm, k0, lane, WS);
        ldBs(Bh_[0], aWh,  0, k0, lane, WS);
        ldBs(Bh_[1], aWh, 16, k0, lane, WS);
        ldBs(Bl_[0], aWl,  0, k0, lane, WS);
        ldBs(Bl_[1], aWl, 16, k0, lane, WS);
        #pragma unroll
        for (int ni = 0; ni < 4; ni++) {
            const uint32_t* bh = &Bh_[ni >> 1][(ni & 1) * 2];
            const uint32_t* bl = &Bl_[ni >> 1][(ni & 1) * 2];
            mma16816(acc[ni], Ah_, bh);
            mma16816(acc[ni], Ah_, bl);
            mma16816(acc[ni], Al_, bh);
        }
    }
    __syncthreads();   // all W reads done before sS aliases the region

    // dump fragments to sS[128][33]
    #pragma unroll
    for (int ni = 0; ni < 4; ni++) {
        int r0 = wm + (lane >> 2);
        int cc = ni * 8 + (lane & 3) * 2;
        sS[r0 * 33 + cc]       = acc[ni][0];
        sS[r0 * 33 + cc + 1]   = acc[ni][1];
        sS[(r0 + 8) * 33 + cc]     = acc[ni][2];
        sS[(r0 + 8) * 33 + cc + 1] = acc[ni][3];
    }
    __syncthreads();

    // per-node epilogue: bias, tanh(q), self-loop weight, q/k fp32 writes
    if (tid < 128) {
        int node = nb + tid;
        if (node < NN) {
            float qv[12], kv[12], sl = 0.f;
            #pragma unroll
            for (int j = 0; j < SMALL; j++) {
                float qj = tanhf(sS[tid * 33 + j] + s_bias[j]);
                float kj = sS[tid * 33 + SMALL + j] + s_bias[SMALL + j];
                qv[j] = qj; kv[j] = kj; sl += qj * kj;
            }
            float4* q4 = (float4*)(g_q + (size_t)node * QS);
            q4[0] = make_float4(qv[0], qv[1], qv[2],  qv[3]);
            q4[1] = make_float4(qv[4], qv[5], qv[6],  qv[7]);
            q4[2] = make_float4(qv[8], qv[9], qv[10], qv[11]);
            float4* k4 = (float4*)(g_k + (size_t)node * QS);
            k4[0] = make_float4(kv[0], kv[1], kv[2],  kv[3]);
            k4[1] = make_float4(kv[4], kv[5], kv[6],  kv[7]);
            k4[2] = make_float4(kv[8], kv[9], kv[10], kv[11]);
            g_csr2[node * CAP] = node;
            g_w2[node * CAP]   = __expf(sl * INV_DK);
            g_fill[node]       = 1;
        }
    }
}

// ---------------- K2: scatter edges + per-edge weight (one atomic) ----------
__device__ __forceinline__ float dotqk(const float* __restrict__ q, const float* __restrict__ k) {
    const float4* q4 = (const float4*)q;
    const float4* k4 = (const float4*)k;
    float4 a = q4[0], b = q4[1], c = q4[2];
    float4 d = k4[0], e = k4[1], f = k4[2];
    return a.x*d.x + a.y*d.y + a.z*d.z + a.w*d.w
         + b.x*e.x + b.y*e.y + b.z*e.z + b.w*e.w
         + c.x*f.x + c.y*f.y + c.z*f.z + c.w*f.w;
}

__global__ void k_scatter(const int* __restrict__ src, const int* __restrict__ dst) {
    int e = blockIdx.x * blockDim.x + threadIdx.x;
    if (e >= NE) return;
    int s = src[e];
    int d = dst[e];
    float w = __expf(dotqk(g_q + s * QS, g_k + d * QS) * INV_DK);
    int p = atomicAdd(&g_fill[d], 1);
    g_csr2[d * CAP + p] = s;
    g_w2[d * CAP + p]   = w;
}

// ---------------- K3: weighted row-gather aggregation (sum folded in) -------
__device__ __forceinline__ void bacc(float4& acc, float w, uint2 p) {
    __nv_bfloat162 lo = *(__nv_bfloat162*)&p.x;
    __nv_bfloat162 hi = *(__nv_bfloat162*)&p.y;
    float2 f0 = __bfloat1622float2(lo);
    float2 f1 = __bfloat1622float2(hi);
    acc.x += w * f0.x; acc.y += w * f0.y;
    acc.z += w * f1.x; acc.w += w * f1.y;
}

__global__ void k_att() {
    int warp = (blockIdx.x * blockDim.x + threadIdx.x) >> 5;
    int lane = threadIdx.x & 31;
    if (warp >= NN) return;
    int deg  = g_fill[warp];
    int base = warp * CAP;

    float4 acc = make_float4(0.f, 0.f, 0.f, 0.f);
    float sw = 0.f;
    int j = 0;
    for (; j + 8 <= deg; j += 8) {
        int ss[8]; float ww[8]; uint2 xx[8];
        #pragma unroll
        for (int u = 0; u < 8; u++) { ss[u] = g_csr2[base+j+u]; ww[u] = g_w2[base+j+u]; }
        #pragma unroll
        for (int u = 0; u < 8; u++) xx[u] = g_Ah[ss[u] * 64 + lane];
        #pragma unroll
        for (int u = 0; u < 8; u++) { bacc(acc, ww[u], xx[u]); sw += ww[u]; }
    }
    for (; j + 4 <= deg; j += 4) {
        int ss[4]; float ww[4]; uint2 xx[4];
        #pragma unroll
        for (int u = 0; u < 4; u++) { ss[u] = g_csr2[base+j+u]; ww[u] = g_w2[base+j+u]; }
        #pragma unroll
        for (int u = 0; u < 4; u++) xx[u] = g_Ah[ss[u] * 64 + lane];
        #pragma unroll
        for (int u = 0; u < 4; u++) { bacc(acc, ww[u], xx[u]); sw += ww[u]; }
    }
    for (; j < deg; j++) {
        float w0 = g_w2[base+j];
        uint2 x0 = g_Ah[g_csr2[base+j] * 64 + lane];
        bacc(acc, w0, x0); sw += w0;
    }
    float invS = 1.f / sw;
    float4 r;
    r.x = acc.x * invS; r.y = acc.y * invS; r.z = acc.z * invS; r.w = acc.w * invS;

    __nv_bfloat16 h0 = __float2bfloat16(r.x), h1 = __float2bfloat16(r.y);
    __nv_bfloat16 h2 = __float2bfloat16(r.z), h3 = __float2bfloat16(r.w);
    __nv_bfloat162 hlo = __halves2bfloat162(h0, h1);
    __nv_bfloat162 hhi = __halves2bfloat162(h2, h3);
    uint2 ph; ph.x = *(unsigned*)&hlo; ph.y = *(unsigned*)&hhi;
    g_Ah[warp * 64 + 32 + lane] = ph;
    __nv_bfloat162 llo = __floats2bfloat162_rn(r.x - __bfloat162float(h0),
                                               r.y - __bfloat162float(h1));
    __nv_bfloat162 lhi = __floats2bfloat162_rn(r.z - __bfloat162float(h2),
                                               r.w - __bfloat162float(h3));
    uint2 pl; pl.x = *(unsigned*)&llo; pl.y = *(unsigned*)&lhi;
    g_Al[warp * 64 + 32 + lane] = pl;
}

// ---------------- K4: PERSISTENT B-resident mma.sync GEMM + norm + relu ------
#define B_STRIDE  264
#define B_MAT_B   (128 * B_STRIDE * 2)
#define A_MAT_B   (128 * 72 * 2)
#define ABUF_B    (2 * A_MAT_B)
#define DYN_SMEM  (2 * B_MAT_B + 2 * ABUF_B)
#define NT        391
#define GRID_OUT  148

__global__ void __launch_bounds__(256, 1) k_out(const float* __restrict__ b2,
                                                float* __restrict__ out) {
    extern __shared__ char dyn[];
    __shared__ float s_b2[128];

    const int tid  = threadIdx.x;
    const int wid  = tid >> 5;
    const int lane = tid & 31;
    const int wm   = (wid & 1) * 64;
    const int wn   = (wid >> 1) * 32;

    if (tid < 128) s_b2[tid] = b2[tid];

    uint32_t sbase0 = smem_u32(dyn);
    uint32_t sBh = sbase0;
    uint32_t sBl = sBh + B_MAT_B;
    uint32_t aBase = sBl + B_MAT_B;
    float* sD = (float*)(dyn + 2 * B_MAT_B);

    const char* Ah8 = (const char*)g_Ah;
    const char* Al8 = (const char*)g_Al;
    const char* Bh8 = (const char*)g_Bh;
    const char* Bl8 = (const char*)g_Bl;

    #pragma unroll
    for (int it = 0; it < 16; it++) {
        int idx = it * 256 + tid;
        int row = idx >> 5, sec = idx & 31;
        uint32_t doff = (uint32_t)row * (B_STRIDE * 2) + sec * 16;
        size_t   soff = (size_t)row * 512 + sec * 16;
        CP_ASYNC16(sBh + doff, Bh8 + soff);
        CP_ASYNC16(sBl + doff, Bl8 + soff);
    }
    CP_COMMIT();

    const int srow = tid >> 3, ssec = tid & 7;
    auto stageA = [&](int t, int c, int b) {
        uint32_t base = aBase + b * ABUF_B;
        int nb = t * 128;
        #pragma unroll
        for (int it = 0; it < 4; it++) {
            int row = srow + it * 32;
            int gm = nb + row; if (gm >= NN) gm = NN - 1;
            uint32_t doff = (uint32_t)(row * 72 + ssec * 8) * 2;
            size_t aoff = ((size_t)gm * 32 + c * 8 + ssec) * 16;
            CP_ASYNC16(base + 0 * A_MAT_B + doff, Ah8 + aoff);
            CP_ASYNC16(base + 1 * A_MAT_B + doff, Al8 + aoff);
        }
        CP_COMMIT();
    };

    for (int t = blockIdx.x; t < NT; t += GRID_OUT) {
        float acc[4][4][4];
        #pragma unroll
        for (int mi = 0; mi < 4; mi++)
            #pragma unroll
            for (int ni = 0; ni < 4; ni++)
                #pragma unroll
                for (int e = 0; e < 4; e++) acc[mi][ni][e] = 0.f;

        stageA(t, 0, 0);

        #pragma unroll 1
        for (int c = 0; c < 4; c++) {
            int b = c & 1;
            if (c < 3) stageA(t, c + 1, b ^ 1);
            if (c < 3) { CP_WAIT(1); } else { CP_WAIT(0); }
            __syncthreads();

            uint32_t sAh = aBase + b * ABUF_B;
            uint32_t sAl = sAh + A_MAT_B;

            #pragma unroll
            for (int ks = 0; ks < 4; ks++) {
                int k0  = ks * 16;
                int k0g = c * 64 + k0;
                uint32_t Ah_[4][4], Al_[4][4], Bh_[2][4], Bl_[2][4];
                #pragma unroll
                for (int mi = 0; mi < 4; mi++) {
                    ldAs(Ah_[mi], sAh, wm + mi * 16, k0, lane, 72);
                    ldAs(Al_[mi], sAl, wm + mi * 16, k0, lane, 72);
                }
                ldBs(Bh_[0], sBh, wn +  0, k0g, lane, B_STRIDE);
                ldBs(Bh_[1], sBh, wn + 16, k0g, lane, B_STRIDE);
                ldBs(Bl_[0], sBl, wn +  0, k0g, lane, B_STRIDE);
                ldBs(Bl_[1], sBl, wn + 16, k0g, lane, B_STRIDE);
                #pragma unroll
                for (int mi = 0; mi < 4; mi++)
                    #pragma unroll
                    for (int ni = 0; ni < 4; ni++) {
                        const uint32_t* bh = &Bh_[ni >> 1][(ni & 1) * 2];
                        const uint32_t* bl = &Bl_[ni >> 1][(ni & 1) * 2];
                        mma16816(acc[mi][ni], Ah_[mi], bh);
                        mma16816(acc[mi][ni], Ah_[mi], bl);
                        mma16816(acc[mi][ni], Al_[mi], bh);
                    }
            }
            __syncthreads();
        }

        #pragma unroll
        for (int mi = 0; mi < 4; mi++)
            #pragma unroll
            for (int ni = 0; ni < 4; ni++) {
                int r0 = wm + mi * 16 + (lane >> 2);
                int cc = wn + ni * 8 + (lane & 3) * 2;
                *(float2*)&sD[r0 * 132 + cc]       = make_float2(acc[mi][ni][0], acc[mi][ni][1]);
                *(float2*)&sD[(r0 + 8) * 132 + cc] = make_float2(acc[mi][ni][2], acc[mi][ni][3]);
            }
        __syncthreads();

        {
            int r = tid >> 1;
            int h = (tid & 1) * 64;
            float vbuf[64];
            float ssq = 0.f;
            #pragma unroll
            for (int g = 0; g < 16; g++) {
                float4 v = *(const float4*)&sD[r * 132 + h + 4 * g];
                v.x += s_b2[h + 4*g+0]; v.y += s_b2[h + 4*g+1];
                v.z += s_b2[h + 4*g+2]; v.w += s_b2[h + 4*g+3];
                vbuf[4*g+0] = v.x; vbuf[4*g+1] = v.y; vbuf[4*g+2] = v.z; vbuf[4*g+3] = v.w;
                ssq += v.x*v.x + v.y*v.y + v.z*v.z + v.w*v.w;
            }
            ssq += __shfl_xor_sync(0xffffffffu, ssq, 1);
            float rn = rsqrtf(ssq);
            int node = t * 128 + r;
            if (node < NN) {
                float* op = out + (size_t)node * 128 + h;
                #pragma unroll
                for (int g = 0; g < 16; g++) {
                    float4 o;
                    o.x = fmaxf(vbuf[4*g+0] * rn, 0.f);
                    o.y = fmaxf(vbuf[4*g+1] * rn, 0.f);
                    o.z = fmaxf(vbuf[4*g+2] * rn, 0.f);
                    o.w = fmaxf(vbuf[4*g+3] * rn, 0.f);
                    *(float4*)(op + 4 * g) = o;
                }
            }
        }
        __syncthreads();
    }
}

// ---------------- launcher (4 launches; ncu capture lands on k_out) ----------
extern "C" void kernel_launch(void* const* d_in, const int* in_sizes, int n_in,
                              void* d_out, int out_size) {
    const float* nd  = (const float*)d_in[0];
    const int*   src = (const int*)  d_in[1];
    const int*   dst = (const int*)  d_in[2];
    const float* Wq  = (const float*)d_in[3];
    const float* bq  = (const float*)d_in[4];
    const float* Wk  = (const float*)d_in[5];
    const float* bk  = (const float*)d_in[6];
    const float* W1  = (const float*)d_in[7];
    const float* W2  = (const float*)d_in[8];
    const float* b2  = (const float*)d_in[9];
    float* out = (float*)d_out;

    static bool init = false;
    if (!init) {
        cudaFuncSetAttribute(k_proj, cudaFuncAttributeMaxDynamicSharedMemorySize, DYN_PROJ);
        cudaFuncSetAttribute(k_out,  cudaFuncAttributeMaxDynamicSharedMemorySize, DYN_SMEM);
        init = true;
    }

    k_proj   <<<PROJ_GRID, 256, DYN_PROJ>>>(nd, Wq, bq, Wk, bk, W1, W2);
    k_scatter<<<(NE + 255) / 256, 256>>>(src, dst);
    k_att    <<<(NN + 7) / 8, 256>>>();
    k_out    <<<GRID_OUT, 256, DYN_SMEM>>>(b2, out);
}